// round 1
// baseline (speedup 1.0000x reference)
#include <cuda_runtime.h>
#include <cuda_bf16.h>
#include <cstdint>
#include <cstddef>

// Problem constants
#define BB 16
#define NN_ 512
#define DD 256
#define HH 8
#define DHH 32
#define EE 16384
#define BN (BB * NN_)          // 8192

// Output layout (flattened tuple, in reference return order)
#define O_AIMG 0
#define O_ATXT 2097152
#define O_XMOD 4194304
#define O_IW   6291456
#define O_TW   10485760
#define O_IC   14680064
#define O_TC   14688256

// -------------------- static scratch (no allocations allowed) --------------------
__device__ float g_qkv[BN * 768];              // packed q|k|v projections
__device__ float g_scores[BB * HH * NN_ * NN_];// 33.5M floats, reused per MHA
__device__ float g_attn[BN * DD];              // attention output pre out-proj
__device__ float g_G1[BN * DD];                // feat @ w1[:256] + b1
__device__ float g_G2[BN * DD];                // feat @ w1[256:]
__device__ float g_H[BN * DD];                 // consistency hidden

// -------------------- generic tiled SGEMM: C = A @ B(^T) + bias, opt ReLU --------
// A: [M,K] row-major (lda). B: NN -> [K,N] (ldb); NT -> [N,K] (ldb). C: [M,N] (ldc).
// M % 64 == 0, N % 64 == 0, K % 32 == 0 guaranteed by problem shapes.
template <bool TRANSB, bool RELU>
__global__ __launch_bounds__(256)
void sgemm_kernel(const float* __restrict__ A, const float* __restrict__ B,
                  const float* __restrict__ bias, float* __restrict__ C,
                  int M, int N, int K, int lda, int ldb, int ldc)
{
    __shared__ float As[32][65];
    __shared__ float Bs[32][65];
    const int tid = threadIdx.x;
    const int tx = tid & 15, ty = tid >> 4;
    const int m0 = blockIdx.y * 64, n0 = blockIdx.x * 64;

    float acc[4][4] = {};

    for (int k0 = 0; k0 < K; k0 += 32) {
        // A tile (transposed into As[k][m])
        {
            const int r  = tid >> 3;
            const int kq = (tid & 7) * 4;
            #pragma unroll
            for (int rr = 0; rr < 2; rr++) {
                const int row = r + rr * 32;
                float4 v = *(const float4*)(A + (size_t)(m0 + row) * lda + k0 + kq);
                As[kq + 0][row] = v.x; As[kq + 1][row] = v.y;
                As[kq + 2][row] = v.z; As[kq + 3][row] = v.w;
            }
        }
        if (TRANSB) {
            const int r  = tid >> 3;
            const int kq = (tid & 7) * 4;
            #pragma unroll
            for (int rr = 0; rr < 2; rr++) {
                const int col = r + rr * 32;
                float4 v = *(const float4*)(B + (size_t)(n0 + col) * ldb + k0 + kq);
                Bs[kq + 0][col] = v.x; Bs[kq + 1][col] = v.y;
                Bs[kq + 2][col] = v.z; Bs[kq + 3][col] = v.w;
            }
        } else {
            const int kk = tid >> 4;
            const int nq = (tid & 15) * 4;
            #pragma unroll
            for (int rr = 0; rr < 2; rr++) {
                const int k = kk + rr * 16;
                float4 v = *(const float4*)(B + (size_t)(k0 + k) * ldb + n0 + nq);
                Bs[k][nq + 0] = v.x; Bs[k][nq + 1] = v.y;
                Bs[k][nq + 2] = v.z; Bs[k][nq + 3] = v.w;
            }
        }
        __syncthreads();

        #pragma unroll
        for (int kk = 0; kk < 32; kk++) {
            float a[4], b[4];
            #pragma unroll
            for (int i = 0; i < 4; i++) a[i] = As[kk][ty * 4 + i];
            #pragma unroll
            for (int j = 0; j < 4; j++) b[j] = Bs[kk][tx * 4 + j];
            #pragma unroll
            for (int i = 0; i < 4; i++)
                #pragma unroll
                for (int j = 0; j < 4; j++)
                    acc[i][j] += a[i] * b[j];
        }
        __syncthreads();
    }

    #pragma unroll
    for (int i = 0; i < 4; i++) {
        const int m = m0 + ty * 4 + i;
        #pragma unroll
        for (int j = 0; j < 4; j++) {
            const int n = n0 + tx * 4 + j;
            float v = acc[i][j];
            if (bias) v += bias[n];
            if (RELU) v = fmaxf(v, 0.0f);
            C[(size_t)m * ldc + n] = v;
        }
    }
}

// -------------------- attention scores: S[b,h,i,j] = q.k/sqrt(dh) + mask -----------
__global__ __launch_bounds__(256)
void scores_kernel(const float* __restrict__ qkv, const float* __restrict__ mask,
                   float* __restrict__ S)
{
    const int bh = blockIdx.z;
    const int b = bh >> 3, h = bh & 7;
    const int i0 = blockIdx.y * 64, j0 = blockIdx.x * 64;
    __shared__ float Qs[32][65];   // [d][i]
    __shared__ float Ks[32][65];   // [d][j]
    const int tid = threadIdx.x;
    {
        const int r  = tid >> 3;
        const int dq = (tid & 7) * 4;
        #pragma unroll
        for (int rr = 0; rr < 2; rr++) {
            const int i = r + rr * 32;
            float4 v = *(const float4*)(qkv + (size_t)(b * NN_ + i0 + i) * 768 + h * DHH + dq);
            Qs[dq + 0][i] = v.x; Qs[dq + 1][i] = v.y; Qs[dq + 2][i] = v.z; Qs[dq + 3][i] = v.w;
        }
        #pragma unroll
        for (int rr = 0; rr < 2; rr++) {
            const int j = r + rr * 32;
            float4 v = *(const float4*)(qkv + (size_t)(b * NN_ + j0 + j) * 768 + 256 + h * DHH + dq);
            Ks[dq + 0][j] = v.x; Ks[dq + 1][j] = v.y; Ks[dq + 2][j] = v.z; Ks[dq + 3][j] = v.w;
        }
    }
    __syncthreads();

    const int tx = tid & 15, ty = tid >> 4;
    float acc[4][4] = {};
    #pragma unroll
    for (int d = 0; d < 32; d++) {
        float a[4], c[4];
        #pragma unroll
        for (int i = 0; i < 4; i++) a[i] = Qs[d][ty * 4 + i];
        #pragma unroll
        for (int j = 0; j < 4; j++) c[j] = Ks[d][tx * 4 + j];
        #pragma unroll
        for (int i = 0; i < 4; i++)
            #pragma unroll
            for (int j = 0; j < 4; j++)
                acc[i][j] += a[i] * c[j];
    }
    const float scale = 0.17677669529663687f;  // 1/sqrt(32)
    #pragma unroll
    for (int i = 0; i < 4; i++) {
        const int gi = i0 + ty * 4 + i;
        #pragma unroll
        for (int j = 0; j < 4; j++) {
            const int gj = j0 + tx * 4 + j;
            float v = acc[i][j] * scale;
            if (mask) v += mask[((size_t)b * NN_ + gi) * NN_ + gj];
            S[((size_t)bh * NN_ + gi) * NN_ + gj] = v;
        }
    }
}

// -------------------- row softmax over 512 ---------------------------------------
__global__ __launch_bounds__(256)
void softmax_kernel(float* __restrict__ S)
{
    __shared__ float red[256];
    const size_t row = blockIdx.x;
    float* p = S + row * NN_;
    const int t = threadIdx.x;
    const float v0 = p[t], v1 = p[t + 256];
    red[t] = fmaxf(v0, v1);
    __syncthreads();
    for (int s = 128; s > 0; s >>= 1) { if (t < s) red[t] = fmaxf(red[t], red[t + s]); __syncthreads(); }
    const float mx = red[0];
    __syncthreads();
    const float e0 = __expf(v0 - mx), e1 = __expf(v1 - mx);
    red[t] = e0 + e1;
    __syncthreads();
    for (int s = 128; s > 0; s >>= 1) { if (t < s) red[t] += red[t + s]; __syncthreads(); }
    const float inv = 1.0f / red[0];
    p[t] = e0 * inv;
    p[t + 256] = e1 * inv;
}

// -------------------- O[b,i,h*32+d] = sum_j A[b,h,i,j] * V[b,j,h,d] ---------------
__global__ __launch_bounds__(256)
void av_kernel(const float* __restrict__ S, const float* __restrict__ qkv,
               float* __restrict__ O)
{
    __shared__ float As[128][65];
    __shared__ float Vs[64][33];
    const int bh = blockIdx.y;
    const int b = bh >> 3, h = bh & 7;
    const int i0 = blockIdx.x * 128;
    const int tid = threadIdx.x;
    const int ty = tid >> 3, tx = tid & 7;   // ty: 0..31 (i quad), tx: 0..7 (d quad)
    float acc[4][4] = {};
    const float* Sbh = S + (size_t)bh * NN_ * NN_;

    for (int j0 = 0; j0 < NN_; j0 += 64) {
        #pragma unroll
        for (int it = 0; it < 8; it++) {
            const int f = tid + it * 256;
            const int row = f >> 4;
            const int c4 = (f & 15) * 4;
            float4 v = *(const float4*)(Sbh + (size_t)(i0 + row) * NN_ + j0 + c4);
            As[row][c4] = v.x; As[row][c4 + 1] = v.y; As[row][c4 + 2] = v.z; As[row][c4 + 3] = v.w;
        }
        #pragma unroll
        for (int it = 0; it < 2; it++) {
            const int jj = (tid >> 3) + it * 32;
            const int dq = (tid & 7) * 4;
            float4 v = *(const float4*)(qkv + (size_t)(b * NN_ + j0 + jj) * 768 + 512 + h * DHH + dq);
            Vs[jj][dq] = v.x; Vs[jj][dq + 1] = v.y; Vs[jj][dq + 2] = v.z; Vs[jj][dq + 3] = v.w;
        }
        __syncthreads();
        #pragma unroll
        for (int jj = 0; jj < 64; jj++) {
            float a[4], vv[4];
            #pragma unroll
            for (int i = 0; i < 4; i++) a[i] = As[ty * 4 + i][jj];
            #pragma unroll
            for (int k = 0; k < 4; k++) vv[k] = Vs[jj][tx * 4 + k];
            #pragma unroll
            for (int i = 0; i < 4; i++)
                #pragma unroll
                for (int k = 0; k < 4; k++)
                    acc[i][k] += a[i] * vv[k];
        }
        __syncthreads();
    }
    #pragma unroll
    for (int i = 0; i < 4; i++) {
        const int gi = i0 + ty * 4 + i;
        #pragma unroll
        for (int k = 0; k < 4; k++)
            O[(size_t)(b * NN_ + gi) * DD + h * DHH + tx * 4 + k] = acc[i][k];
    }
}

// -------------------- edge MLP: sigmoid( relu(G1[src]+G2[dst]) . w2 + b2 ) --------
__global__ __launch_bounds__(256)
void edge_kernel(const float* __restrict__ G1, const float* __restrict__ G2,
                 const int* __restrict__ src, const int* __restrict__ dst,
                 const float* __restrict__ w2, const float* __restrict__ b2,
                 float* __restrict__ W)
{
    const int b = blockIdx.y;
    const int e = blockIdx.x * 8 + (threadIdx.x >> 5);
    const int lane = threadIdx.x & 31;
    const int s = src[e], d = dst[e];
    const float* g1 = G1 + ((size_t)b * NN_ + s) * DD;
    const float* g2 = G2 + ((size_t)b * NN_ + d) * DD;
    float acc = 0.0f;
    #pragma unroll
    for (int q = 0; q < 2; q++) {
        const int t = lane * 8 + q * 4;
        float4 a = *(const float4*)(g1 + t);
        float4 c = *(const float4*)(g2 + t);
        float4 w = *(const float4*)(w2 + t);
        acc += fmaxf(a.x + c.x, 0.0f) * w.x + fmaxf(a.y + c.y, 0.0f) * w.y
             + fmaxf(a.z + c.z, 0.0f) * w.z + fmaxf(a.w + c.w, 0.0f) * w.w;
    }
    #pragma unroll
    for (int o = 16; o > 0; o >>= 1) acc += __shfl_xor_sync(0xffffffffu, acc, o);
    if (lane == 0) {
        const float v = 1.0f / (1.0f + __expf(-(acc + b2[0])));
        W[((size_t)b * NN_ + s) * NN_ + d] = v;
    }
}

// -------------------- consistency reduce: sigmoid(H . cw2 + cb2) -------------------
__global__ __launch_bounds__(256)
void cons_reduce_kernel(const float* __restrict__ Hbuf, const float* __restrict__ cw2,
                        const float* __restrict__ cb2, float* __restrict__ out)
{
    __shared__ float red[256];
    const int row = blockIdx.x;
    const int t = threadIdx.x;
    red[t] = Hbuf[(size_t)row * DD + t] * __ldg(cw2 + t);
    __syncthreads();
    for (int s = 128; s > 0; s >>= 1) { if (t < s) red[t] += red[t + s]; __syncthreads(); }
    if (t == 0) out[row] = 1.0f / (1.0f + __expf(-(red[0] + cb2[0])));
}

// -------------------- zero fill ----------------------------------------------------
__global__ void zero_kernel(float* __restrict__ p, size_t n)
{
    size_t i = (size_t)blockIdx.x * blockDim.x + threadIdx.x;
    const size_t stride = (size_t)gridDim.x * blockDim.x;
    for (; i < n; i += stride) p[i] = 0.0f;
}

// ===================================================================================
extern "C" void kernel_launch(void* const* d_in, const int* in_sizes, int n_in,
                              void* d_out, int out_size)
{
    const float* img   = (const float*)d_in[0];
    const float* txt   = (const float*)d_in[1];
    const int*   src   = (const int*)d_in[2];
    const int*   dst   = (const int*)d_in[3];
    const float* w1    = (const float*)d_in[4];
    const float* b1    = (const float*)d_in[5];
    const float* w2    = (const float*)d_in[6];
    const float* b2    = (const float*)d_in[7];
    const float* in_w  = (const float*)d_in[8];
    const float* in_b  = (const float*)d_in[9];
    const float* out_w = (const float*)d_in[10];
    const float* out_b = (const float*)d_in[11];
    const float* cw1   = (const float*)d_in[12];
    const float* cb1   = (const float*)d_in[13];
    const float* cw2   = (const float*)d_in[14];
    const float* cb2   = (const float*)d_in[15];
    float* out = (float*)d_out;

    float *qkv, *scores, *attn, *G1, *G2, *Hb;
    cudaGetSymbolAddress((void**)&qkv,    g_qkv);
    cudaGetSymbolAddress((void**)&scores, g_scores);
    cudaGetSymbolAddress((void**)&attn,   g_attn);
    cudaGetSymbolAddress((void**)&G1,     g_G1);
    cudaGetSymbolAddress((void**)&G2,     g_G2);
    cudaGetSymbolAddress((void**)&Hb,     g_H);

    const dim3 blk(256);
    const dim3 g_gemm256(256 / 64, BN / 64);   // N=256
    const dim3 g_gemm512(512 / 64, BN / 64);   // N=512
    const dim3 g_gemm768(768 / 64, BN / 64);   // N=768
    const dim3 g_scores(8, 8, BB * HH);
    const dim3 g_av(NN_ / 128, BB * HH);
    const dim3 g_edge(EE / 8, BB);

    // ---- zero the two adjacency-weight output blocks (contiguous) ----
    zero_kernel<<<2048, 256>>>(out + O_IW, (size_t)2 * BB * NN_ * NN_);

    // ---- causal weights (algebraic split: G1 = f@w1[:256]+b1, G2 = f@w1[256:]) ----
    // img
    sgemm_kernel<false, false><<<g_gemm256, blk>>>(img, w1,            b1,      G1, BN, 256, 256, 256, 256, 256);
    sgemm_kernel<false, false><<<g_gemm256, blk>>>(img, w1 + 256*256, nullptr,  G2, BN, 256, 256, 256, 256, 256);
    edge_kernel<<<g_edge, blk>>>(G1, G2, src, dst, w2, b2, out + O_IW);
    // text
    sgemm_kernel<false, false><<<g_gemm256, blk>>>(txt, w1,            b1,      G1, BN, 256, 256, 256, 256, 256);
    sgemm_kernel<false, false><<<g_gemm256, blk>>>(txt, w1 + 256*256, nullptr,  G2, BN, 256, 256, 256, 256, 256);
    edge_kernel<<<g_edge, blk>>>(G1, G2, src, dst, w2, b2, out + O_TW);

    // ---- MHA 1: attended_img = MHA(img, img, img, mask=img_weights) ----
    sgemm_kernel<true, false><<<g_gemm768, blk>>>(img, in_w, in_b, qkv, BN, 768, 256, 256, 256, 768);
    scores_kernel<<<g_scores, blk>>>(qkv, out + O_IW, scores);
    softmax_kernel<<<BB * HH * NN_, blk>>>(scores);
    av_kernel<<<g_av, blk>>>(scores, qkv, attn);
    sgemm_kernel<true, false><<<g_gemm256, blk>>>(attn, out_w, out_b, out + O_AIMG, BN, 256, 256, 256, 256, 256);

    // ---- MHA 2: attended_text = MHA(txt, txt, txt, mask=text_weights) ----
    sgemm_kernel<true, false><<<g_gemm768, blk>>>(txt, in_w, in_b, qkv, BN, 768, 256, 256, 256, 768);
    scores_kernel<<<g_scores, blk>>>(qkv, out + O_TW, scores);
    softmax_kernel<<<BB * HH * NN_, blk>>>(scores);
    av_kernel<<<g_av, blk>>>(scores, qkv, attn);
    sgemm_kernel<true, false><<<g_gemm256, blk>>>(attn, out_w, out_b, out + O_ATXT, BN, 256, 256, 256, 256, 256);

    // ---- MHA 3: cross_modal = MHA(attended_img, attended_text, attended_text) ----
    // q from attended_img (in_w rows 0..255), k|v from attended_text (rows 256..767)
    sgemm_kernel<true, false><<<g_gemm256, blk>>>(out + O_AIMG, in_w,           in_b,       qkv,       BN, 256, 256, 256, 256, 768);
    sgemm_kernel<true, false><<<g_gemm512, blk>>>(out + O_ATXT, in_w + 256*256, in_b + 256, qkv + 256, BN, 512, 256, 256, 256, 768);
    scores_kernel<<<g_scores, blk>>>(qkv, nullptr, scores);
    softmax_kernel<<<BB * HH * NN_, blk>>>(scores);
    av_kernel<<<g_av, blk>>>(scores, qkv, attn);
    sgemm_kernel<true, false><<<g_gemm256, blk>>>(attn, out_w, out_b, out + O_XMOD, BN, 256, 256, 256, 256, 256);

    // ---- consistency heads ----
    sgemm_kernel<false, true><<<g_gemm256, blk>>>(out + O_AIMG, cw1, cb1, Hb, BN, 256, 256, 256, 256, 256);
    cons_reduce_kernel<<<BN, blk>>>(Hb, cw2, cb2, out + O_IC);
    sgemm_kernel<false, true><<<g_gemm256, blk>>>(out + O_ATXT, cw1, cb1, Hb, BN, 256, 256, 256, 256, 256);
    cons_reduce_kernel<<<BN, blk>>>(Hb, cw2, cb2, out + O_TC);
}

// round 2
// speedup vs baseline: 1.2932x; 1.2932x over previous
#include <cuda_runtime.h>
#include <cuda_bf16.h>
#include <cstdint>
#include <cstddef>

// Problem constants
#define BB 16
#define NN_ 512
#define DD 256
#define HH 8
#define DHH 32
#define EE 16384
#define BN (BB * NN_)          // 8192

// Output layout (flattened tuple, in reference return order)
#define O_AIMG 0
#define O_ATXT 2097152
#define O_XMOD 4194304
#define O_IW   6291456
#define O_TW   10485760
#define O_IC   14680064
#define O_TC   14688256

// -------------------- static scratch (no allocations allowed) --------------------
__device__ float g_qkv[BN * 768];              // packed q|k|v projections
__device__ float g_scores[BB * HH * NN_ * NN_];// 33.5M floats, reused per MHA
__device__ float g_attn[BN * DD];              // attention output pre out-proj
__device__ float g_G1[BN * DD];                // feat @ w1[:256] + b1
__device__ float g_G2[BN * DD];                // feat @ w1[256:]
__device__ float g_H[BN * DD];                 // consistency hidden

// ============================ TF32 tensor-core GEMM ================================
// C[M,N] = A[M,K] @ B(^T) + bias, optional ReLU.  fp32 in/out, tf32 MMA inside.
// CTA tile 128x128, k-step 32. 8 warps: warp_m = wid>>1 (4), warp_n = wid&1 (2),
// each warp owns 32x64 = 2 (m16) x 8 (n8) mma tiles.
// Requires M%128==0, N%128==0, K%32==0 (true for all uses here).

__device__ __forceinline__ uint32_t f32_to_tf32(float x) {
    uint32_t r;
    asm("cvt.rna.tf32.f32 %0, %1;" : "=r"(r) : "f"(x));
    return r;
}

__device__ __forceinline__ void mma_tf32(float* d, const uint32_t* a, const uint32_t* b) {
    asm volatile(
        "mma.sync.aligned.m16n8k8.row.col.f32.tf32.tf32.f32 "
        "{%0,%1,%2,%3}, {%4,%5,%6,%7}, {%8,%9}, {%0,%1,%2,%3};"
        : "+f"(d[0]), "+f"(d[1]), "+f"(d[2]), "+f"(d[3])
        : "r"(a[0]), "r"(a[1]), "r"(a[2]), "r"(a[3]), "r"(b[0]), "r"(b[1]));
}

template <bool TRANSB, bool RELU>
__global__ __launch_bounds__(256)
void gemm_tf32_kernel(const float* __restrict__ A, const float* __restrict__ B,
                      const float* __restrict__ bias, float* __restrict__ C,
                      int M, int N, int K, int lda, int ldb, int ldc)
{
    // pitch 136: bank = (8*k + m) % 32 -> conflict-free fragment reads
    __shared__ uint32_t As[32][136];   // [k][m]  (tf32 bits)
    __shared__ uint32_t Bs[32][136];   // [k][n]  (tf32 bits)

    const int tid  = threadIdx.x;
    const int wid  = tid >> 5;
    const int lane = tid & 31;
    const int g    = lane >> 2;        // 0..7
    const int c    = lane & 3;         // 0..3
    const int warp_m = wid >> 1;       // 0..3  -> 32-row slab
    const int warp_n = wid & 1;        // 0..1  -> 64-col slab
    const int m0 = blockIdx.y * 128;
    const int n0 = blockIdx.x * 128;

    float acc[2][8][4];
    #pragma unroll
    for (int i = 0; i < 2; i++)
        #pragma unroll
        for (int j = 0; j < 8; j++)
            #pragma unroll
            for (int q = 0; q < 4; q++) acc[i][j][q] = 0.0f;

    for (int k0 = 0; k0 < K; k0 += 32) {
        // ---- load A tile: rows m0..m0+127, k0..k0+31 -> As[k][m] ----
        {
            const int m   = tid & 127;
            const int kq0 = tid >> 7;          // 0..1
            const float* ap = A + (size_t)(m0 + m) * lda + k0;
            #pragma unroll
            for (int it = 0; it < 4; it++) {
                const int kq = kq0 + it * 2;   // 0..7
                float4 v = *(const float4*)(ap + kq * 4);
                As[kq * 4 + 0][m] = f32_to_tf32(v.x);
                As[kq * 4 + 1][m] = f32_to_tf32(v.y);
                As[kq * 4 + 2][m] = f32_to_tf32(v.z);
                As[kq * 4 + 3][m] = f32_to_tf32(v.w);
            }
        }
        // ---- load B tile -> Bs[k][n] ----
        if (TRANSB) {   // B is [N][K] row-major
            const int n   = tid & 127;
            const int kq0 = tid >> 7;
            const float* bp = B + (size_t)(n0 + n) * ldb + k0;
            #pragma unroll
            for (int it = 0; it < 4; it++) {
                const int kq = kq0 + it * 2;
                float4 v = *(const float4*)(bp + kq * 4);
                Bs[kq * 4 + 0][n] = f32_to_tf32(v.x);
                Bs[kq * 4 + 1][n] = f32_to_tf32(v.y);
                Bs[kq * 4 + 2][n] = f32_to_tf32(v.z);
                Bs[kq * 4 + 3][n] = f32_to_tf32(v.w);
            }
        } else {        // B is [K][N] row-major
            const int k  = tid >> 3;           // 0..31
            const int nq0 = tid & 7;
            const float* bp = B + (size_t)(k0 + k) * ldb + n0;
            #pragma unroll
            for (int it = 0; it < 4; it++) {
                const int n4 = (nq0 + it * 8) * 4;
                float4 v = *(const float4*)(bp + n4);
                uint4 t;
                t.x = f32_to_tf32(v.x); t.y = f32_to_tf32(v.y);
                t.z = f32_to_tf32(v.z); t.w = f32_to_tf32(v.w);
                *(uint4*)&Bs[k][n4] = t;
            }
        }
        __syncthreads();

        #pragma unroll
        for (int kb = 0; kb < 4; kb++) {
            const int kk = kb * 8;
            uint32_t a[2][4];
            #pragma unroll
            for (int mt = 0; mt < 2; mt++) {
                const int m = warp_m * 32 + mt * 16 + g;
                a[mt][0] = As[kk + c    ][m];
                a[mt][1] = As[kk + c    ][m + 8];
                a[mt][2] = As[kk + c + 4][m];
                a[mt][3] = As[kk + c + 4][m + 8];
            }
            uint32_t b[8][2];
            #pragma unroll
            for (int nt = 0; nt < 8; nt++) {
                const int n = warp_n * 64 + nt * 8 + g;
                b[nt][0] = Bs[kk + c    ][n];
                b[nt][1] = Bs[kk + c + 4][n];
            }
            #pragma unroll
            for (int mt = 0; mt < 2; mt++)
                #pragma unroll
                for (int nt = 0; nt < 8; nt++)
                    mma_tf32(acc[mt][nt], a[mt], b[nt]);
        }
        __syncthreads();
    }

    // ---- epilogue ----
    #pragma unroll
    for (int mt = 0; mt < 2; mt++) {
        const int r0 = m0 + warp_m * 32 + mt * 16 + g;
        #pragma unroll
        for (int nt = 0; nt < 8; nt++) {
            const int col = n0 + warp_n * 64 + nt * 8 + 2 * c;
            float2 bv = make_float2(0.f, 0.f);
            if (bias) bv = *(const float2*)(bias + col);
            float2 v0 = make_float2(acc[mt][nt][0] + bv.x, acc[mt][nt][1] + bv.y);
            float2 v1 = make_float2(acc[mt][nt][2] + bv.x, acc[mt][nt][3] + bv.y);
            if (RELU) {
                v0.x = fmaxf(v0.x, 0.f); v0.y = fmaxf(v0.y, 0.f);
                v1.x = fmaxf(v1.x, 0.f); v1.y = fmaxf(v1.y, 0.f);
            }
            *(float2*)(C + (size_t)r0 * ldc + col)       = v0;
            *(float2*)(C + (size_t)(r0 + 8) * ldc + col) = v1;
        }
    }
}

// -------------------- attention scores: S[b,h,i,j] = q.k/sqrt(dh) + mask -----------
__global__ __launch_bounds__(256)
void scores_kernel(const float* __restrict__ qkv, const float* __restrict__ mask,
                   float* __restrict__ S)
{
    const int bh = blockIdx.z;
    const int b = bh >> 3, h = bh & 7;
    const int i0 = blockIdx.y * 64, j0 = blockIdx.x * 64;
    __shared__ float Qs[32][65];   // [d][i]
    __shared__ float Ks[32][65];   // [d][j]
    const int tid = threadIdx.x;
    {
        const int r  = tid >> 3;
        const int dq = (tid & 7) * 4;
        #pragma unroll
        for (int rr = 0; rr < 2; rr++) {
            const int i = r + rr * 32;
            float4 v = *(const float4*)(qkv + (size_t)(b * NN_ + i0 + i) * 768 + h * DHH + dq);
            Qs[dq + 0][i] = v.x; Qs[dq + 1][i] = v.y; Qs[dq + 2][i] = v.z; Qs[dq + 3][i] = v.w;
        }
        #pragma unroll
        for (int rr = 0; rr < 2; rr++) {
            const int j = r + rr * 32;
            float4 v = *(const float4*)(qkv + (size_t)(b * NN_ + j0 + j) * 768 + 256 + h * DHH + dq);
            Ks[dq + 0][j] = v.x; Ks[dq + 1][j] = v.y; Ks[dq + 2][j] = v.z; Ks[dq + 3][j] = v.w;
        }
    }
    __syncthreads();

    const int tx = tid & 15, ty = tid >> 4;
    float acc[4][4] = {};
    #pragma unroll
    for (int d = 0; d < 32; d++) {
        float a[4], cc[4];
        #pragma unroll
        for (int i = 0; i < 4; i++) a[i] = Qs[d][ty * 4 + i];
        #pragma unroll
        for (int j = 0; j < 4; j++) cc[j] = Ks[d][tx * 4 + j];
        #pragma unroll
        for (int i = 0; i < 4; i++)
            #pragma unroll
            for (int j = 0; j < 4; j++)
                acc[i][j] += a[i] * cc[j];
    }
    const float scale = 0.17677669529663687f;  // 1/sqrt(32)
    #pragma unroll
    for (int i = 0; i < 4; i++) {
        const int gi = i0 + ty * 4 + i;
        #pragma unroll
        for (int j = 0; j < 4; j++) {
            const int gj = j0 + tx * 4 + j;
            float v = acc[i][j] * scale;
            if (mask) v += mask[((size_t)b * NN_ + gi) * NN_ + gj];
            S[((size_t)bh * NN_ + gi) * NN_ + gj] = v;
        }
    }
}

// -------------------- row softmax over 512 ---------------------------------------
__global__ __launch_bounds__(256)
void softmax_kernel(float* __restrict__ S)
{
    __shared__ float red[256];
    const size_t row = blockIdx.x;
    float* p = S + row * NN_;
    const int t = threadIdx.x;
    const float v0 = p[t], v1 = p[t + 256];
    red[t] = fmaxf(v0, v1);
    __syncthreads();
    for (int s = 128; s > 0; s >>= 1) { if (t < s) red[t] = fmaxf(red[t], red[t + s]); __syncthreads(); }
    const float mx = red[0];
    __syncthreads();
    const float e0 = __expf(v0 - mx), e1 = __expf(v1 - mx);
    red[t] = e0 + e1;
    __syncthreads();
    for (int s = 128; s > 0; s >>= 1) { if (t < s) red[t] += red[t + s]; __syncthreads(); }
    const float inv = 1.0f / red[0];
    p[t] = e0 * inv;
    p[t + 256] = e1 * inv;
}

// -------------------- O[b,i,h*32+d] = sum_j A[b,h,i,j] * V[b,j,h,d] ---------------
__global__ __launch_bounds__(256)
void av_kernel(const float* __restrict__ S, const float* __restrict__ qkv,
               float* __restrict__ O)
{
    __shared__ float As[128][65];
    __shared__ float Vs[64][33];
    const int bh = blockIdx.y;
    const int b = bh >> 3, h = bh & 7;
    const int i0 = blockIdx.x * 128;
    const int tid = threadIdx.x;
    const int ty = tid >> 3, tx = tid & 7;   // ty: 0..31 (i quad), tx: 0..7 (d quad)
    float acc[4][4] = {};
    const float* Sbh = S + (size_t)bh * NN_ * NN_;

    for (int j0 = 0; j0 < NN_; j0 += 64) {
        #pragma unroll
        for (int it = 0; it < 8; it++) {
            const int f = tid + it * 256;
            const int row = f >> 4;
            const int c4 = (f & 15) * 4;
            float4 v = *(const float4*)(Sbh + (size_t)(i0 + row) * NN_ + j0 + c4);
            As[row][c4] = v.x; As[row][c4 + 1] = v.y; As[row][c4 + 2] = v.z; As[row][c4 + 3] = v.w;
        }
        #pragma unroll
        for (int it = 0; it < 2; it++) {
            const int jj = (tid >> 3) + it * 32;
            const int dq = (tid & 7) * 4;
            float4 v = *(const float4*)(qkv + (size_t)(b * NN_ + j0 + jj) * 768 + 512 + h * DHH + dq);
            Vs[jj][dq] = v.x; Vs[jj][dq + 1] = v.y; Vs[jj][dq + 2] = v.z; Vs[jj][dq + 3] = v.w;
        }
        __syncthreads();
        #pragma unroll
        for (int jj = 0; jj < 64; jj++) {
            float a[4], vv[4];
            #pragma unroll
            for (int i = 0; i < 4; i++) a[i] = As[ty * 4 + i][jj];
            #pragma unroll
            for (int k = 0; k < 4; k++) vv[k] = Vs[jj][tx * 4 + k];
            #pragma unroll
            for (int i = 0; i < 4; i++)
                #pragma unroll
                for (int k = 0; k < 4; k++)
                    acc[i][k] += a[i] * vv[k];
        }
        __syncthreads();
    }
    #pragma unroll
    for (int i = 0; i < 4; i++) {
        const int gi = i0 + ty * 4 + i;
        #pragma unroll
        for (int k = 0; k < 4; k++)
            O[(size_t)(b * NN_ + gi) * DD + h * DHH + tx * 4 + k] = acc[i][k];
    }
}

// -------------------- edge MLP: sigmoid( relu(G1[src]+G2[dst]) . w2 + b2 ) --------
__global__ __launch_bounds__(256)
void edge_kernel(const float* __restrict__ G1, const float* __restrict__ G2,
                 const int* __restrict__ src, const int* __restrict__ dst,
                 const float* __restrict__ w2, const float* __restrict__ b2,
                 float* __restrict__ W)
{
    const int b = blockIdx.y;
    const int e = blockIdx.x * 8 + (threadIdx.x >> 5);
    const int lane = threadIdx.x & 31;
    const int s = src[e], d = dst[e];
    const float* g1 = G1 + ((size_t)b * NN_ + s) * DD;
    const float* g2 = G2 + ((size_t)b * NN_ + d) * DD;
    float acc = 0.0f;
    #pragma unroll
    for (int q = 0; q < 2; q++) {
        const int t = lane * 8 + q * 4;
        float4 a = *(const float4*)(g1 + t);
        float4 c = *(const float4*)(g2 + t);
        float4 w = *(const float4*)(w2 + t);
        acc += fmaxf(a.x + c.x, 0.0f) * w.x + fmaxf(a.y + c.y, 0.0f) * w.y
             + fmaxf(a.z + c.z, 0.0f) * w.z + fmaxf(a.w + c.w, 0.0f) * w.w;
    }
    #pragma unroll
    for (int o = 16; o > 0; o >>= 1) acc += __shfl_xor_sync(0xffffffffu, acc, o);
    if (lane == 0) {
        const float v = 1.0f / (1.0f + __expf(-(acc + b2[0])));
        W[((size_t)b * NN_ + s) * NN_ + d] = v;
    }
}

// -------------------- consistency reduce: sigmoid(H . cw2 + cb2) -------------------
__global__ __launch_bounds__(256)
void cons_reduce_kernel(const float* __restrict__ Hbuf, const float* __restrict__ cw2,
                        const float* __restrict__ cb2, float* __restrict__ out)
{
    __shared__ float red[256];
    const int row = blockIdx.x;
    const int t = threadIdx.x;
    red[t] = Hbuf[(size_t)row * DD + t] * __ldg(cw2 + t);
    __syncthreads();
    for (int s = 128; s > 0; s >>= 1) { if (t < s) red[t] += red[t + s]; __syncthreads(); }
    if (t == 0) out[row] = 1.0f / (1.0f + __expf(-(red[0] + cb2[0])));
}

// -------------------- zero fill ----------------------------------------------------
__global__ void zero_kernel(float* __restrict__ p, size_t n)
{
    size_t i = (size_t)blockIdx.x * blockDim.x + threadIdx.x;
    const size_t stride = (size_t)gridDim.x * blockDim.x;
    for (; i < n; i += stride) p[i] = 0.0f;
}

// ===================================================================================
extern "C" void kernel_launch(void* const* d_in, const int* in_sizes, int n_in,
                              void* d_out, int out_size)
{
    const float* img   = (const float*)d_in[0];
    const float* txt   = (const float*)d_in[1];
    const int*   src   = (const int*)d_in[2];
    const int*   dst   = (const int*)d_in[3];
    const float* w1    = (const float*)d_in[4];
    const float* b1    = (const float*)d_in[5];
    const float* w2    = (const float*)d_in[6];
    const float* b2    = (const float*)d_in[7];
    const float* in_w  = (const float*)d_in[8];
    const float* in_b  = (const float*)d_in[9];
    const float* out_w = (const float*)d_in[10];
    const float* out_b = (const float*)d_in[11];
    const float* cw1   = (const float*)d_in[12];
    const float* cb1   = (const float*)d_in[13];
    const float* cw2   = (const float*)d_in[14];
    const float* cb2   = (const float*)d_in[15];
    float* out = (float*)d_out;

    float *qkv, *scores, *attn, *G1, *G2, *Hb;
    cudaGetSymbolAddress((void**)&qkv,    g_qkv);
    cudaGetSymbolAddress((void**)&scores, g_scores);
    cudaGetSymbolAddress((void**)&attn,   g_attn);
    cudaGetSymbolAddress((void**)&G1,     g_G1);
    cudaGetSymbolAddress((void**)&G2,     g_G2);
    cudaGetSymbolAddress((void**)&Hb,     g_H);

    const dim3 blk(256);
    const dim3 g_gemm256(256 / 128, BN / 128);   // (2, 64)
    const dim3 g_gemm512(512 / 128, BN / 128);   // (4, 64)
    const dim3 g_gemm768(768 / 128, BN / 128);   // (6, 64)
    const dim3 g_scores(8, 8, BB * HH);
    const dim3 g_av(NN_ / 128, BB * HH);
    const dim3 g_edge(EE / 8, BB);

    // ---- zero the two adjacency-weight output blocks (contiguous) ----
    zero_kernel<<<2048, 256>>>(out + O_IW, (size_t)2 * BB * NN_ * NN_);

    // ---- causal weights (algebraic split: G1 = f@w1[:256]+b1, G2 = f@w1[256:]) ----
    // img
    gemm_tf32_kernel<false, false><<<g_gemm256, blk>>>(img, w1,            b1,      G1, BN, 256, 256, 256, 256, 256);
    gemm_tf32_kernel<false, false><<<g_gemm256, blk>>>(img, w1 + 256*256, nullptr,  G2, BN, 256, 256, 256, 256, 256);
    edge_kernel<<<g_edge, blk>>>(G1, G2, src, dst, w2, b2, out + O_IW);
    // text
    gemm_tf32_kernel<false, false><<<g_gemm256, blk>>>(txt, w1,            b1,      G1, BN, 256, 256, 256, 256, 256);
    gemm_tf32_kernel<false, false><<<g_gemm256, blk>>>(txt, w1 + 256*256, nullptr,  G2, BN, 256, 256, 256, 256, 256);
    edge_kernel<<<g_edge, blk>>>(G1, G2, src, dst, w2, b2, out + O_TW);

    // ---- MHA 1: attended_img = MHA(img, img, img, mask=img_weights) ----
    gemm_tf32_kernel<true, false><<<g_gemm768, blk>>>(img, in_w, in_b, qkv, BN, 768, 256, 256, 256, 768);
    scores_kernel<<<g_scores, blk>>>(qkv, out + O_IW, scores);
    softmax_kernel<<<BB * HH * NN_, blk>>>(scores);
    av_kernel<<<g_av, blk>>>(scores, qkv, attn);
    gemm_tf32_kernel<true, false><<<g_gemm256, blk>>>(attn, out_w, out_b, out + O_AIMG, BN, 256, 256, 256, 256, 256);

    // ---- MHA 2: attended_text = MHA(txt, txt, txt, mask=text_weights) ----
    gemm_tf32_kernel<true, false><<<g_gemm768, blk>>>(txt, in_w, in_b, qkv, BN, 768, 256, 256, 256, 768);
    scores_kernel<<<g_scores, blk>>>(qkv, out + O_TW, scores);
    softmax_kernel<<<BB * HH * NN_, blk>>>(scores);
    av_kernel<<<g_av, blk>>>(scores, qkv, attn);
    gemm_tf32_kernel<true, false><<<g_gemm256, blk>>>(attn, out_w, out_b, out + O_ATXT, BN, 256, 256, 256, 256, 256);

    // ---- MHA 3: cross_modal = MHA(attended_img, attended_text, attended_text) ----
    // q from attended_img (in_w rows 0..255), k|v from attended_text (rows 256..767)
    gemm_tf32_kernel<true, false><<<g_gemm256, blk>>>(out + O_AIMG, in_w,           in_b,       qkv,       BN, 256, 256, 256, 256, 768);
    gemm_tf32_kernel<true, false><<<g_gemm512, blk>>>(out + O_ATXT, in_w + 256*256, in_b + 256, qkv + 256, BN, 512, 256, 256, 256, 768);
    scores_kernel<<<g_scores, blk>>>(qkv, nullptr, scores);
    softmax_kernel<<<BB * HH * NN_, blk>>>(scores);
    av_kernel<<<g_av, blk>>>(scores, qkv, attn);
    gemm_tf32_kernel<true, false><<<g_gemm256, blk>>>(attn, out_w, out_b, out + O_XMOD, BN, 256, 256, 256, 256, 256);

    // ---- consistency heads ----
    gemm_tf32_kernel<false, true><<<g_gemm256, blk>>>(out + O_AIMG, cw1, cb1, Hb, BN, 256, 256, 256, 256, 256);
    cons_reduce_kernel<<<BN, blk>>>(Hb, cw2, cb2, out + O_IC);
    gemm_tf32_kernel<false, true><<<g_gemm256, blk>>>(out + O_ATXT, cw1, cb1, Hb, BN, 256, 256, 256, 256, 256);
    cons_reduce_kernel<<<BN, blk>>>(Hb, cw2, cb2, out + O_TC);
}

// round 3
// speedup vs baseline: 2.3435x; 1.8122x over previous
#include <cuda_runtime.h>
#include <cuda_bf16.h>
#include <cstdint>
#include <cstddef>

// Problem constants
#define BB 16
#define NN_ 512
#define DD 256
#define HH 8
#define DHH 32
#define EE 16384
#define BN (BB * NN_)          // 8192

// Output layout (flattened tuple, in reference return order)
#define O_AIMG 0
#define O_ATXT 2097152
#define O_XMOD 4194304
#define O_IW   6291456
#define O_TW   10485760
#define O_IC   14680064
#define O_TC   14688256

// -------------------- static scratch (no allocations allowed) --------------------
__device__ float g_qkv[BN * 768];              // packed q|k|v projections
__device__ float g_attn[BN * DD];              // attention output pre out-proj
__device__ float g_G1[BN * DD];                // feat @ w1[:256] + b1
__device__ float g_G2[BN * DD];                // feat @ w1[256:]
__device__ float g_H[BN * DD];                 // consistency hidden

__device__ __forceinline__ uint32_t f32_to_tf32(float x) {
    uint32_t r;
    asm("cvt.rna.tf32.f32 %0, %1;" : "=r"(r) : "f"(x));
    return r;
}

__device__ __forceinline__ void mma_tf32(float* d, const uint32_t* a, const uint32_t* b) {
    asm volatile(
        "mma.sync.aligned.m16n8k8.row.col.f32.tf32.tf32.f32 "
        "{%0,%1,%2,%3}, {%4,%5,%6,%7}, {%8,%9}, {%0,%1,%2,%3};"
        : "+f"(d[0]), "+f"(d[1]), "+f"(d[2]), "+f"(d[3])
        : "r"(a[0]), "r"(a[1]), "r"(a[2]), "r"(a[3]), "r"(b[0]), "r"(b[1]));
}

// ============================ TF32 tensor-core GEMM ================================
// C[M,N] = A[M,K] @ B(^T) + bias, optional ReLU.  fp32 in/out, tf32 MMA inside.
template <bool TRANSB, bool RELU>
__global__ __launch_bounds__(256)
void gemm_tf32_kernel(const float* __restrict__ A, const float* __restrict__ B,
                      const float* __restrict__ bias, float* __restrict__ C,
                      int M, int N, int K, int lda, int ldb, int ldc)
{
    __shared__ uint32_t As[32][136];   // [k][m]  (tf32 bits)
    __shared__ uint32_t Bs[32][136];   // [k][n]  (tf32 bits)

    const int tid  = threadIdx.x;
    const int wid  = tid >> 5;
    const int lane = tid & 31;
    const int g    = lane >> 2;
    const int c    = lane & 3;
    const int warp_m = wid >> 1;
    const int warp_n = wid & 1;
    const int m0 = blockIdx.y * 128;
    const int n0 = blockIdx.x * 128;

    float acc[2][8][4];
    #pragma unroll
    for (int i = 0; i < 2; i++)
        #pragma unroll
        for (int j = 0; j < 8; j++)
            #pragma unroll
            for (int q = 0; q < 4; q++) acc[i][j][q] = 0.0f;

    for (int k0 = 0; k0 < K; k0 += 32) {
        {
            const int m   = tid & 127;
            const int kq0 = tid >> 7;
            const float* ap = A + (size_t)(m0 + m) * lda + k0;
            #pragma unroll
            for (int it = 0; it < 4; it++) {
                const int kq = kq0 + it * 2;
                float4 v = *(const float4*)(ap + kq * 4);
                As[kq * 4 + 0][m] = f32_to_tf32(v.x);
                As[kq * 4 + 1][m] = f32_to_tf32(v.y);
                As[kq * 4 + 2][m] = f32_to_tf32(v.z);
                As[kq * 4 + 3][m] = f32_to_tf32(v.w);
            }
        }
        if (TRANSB) {
            const int n   = tid & 127;
            const int kq0 = tid >> 7;
            const float* bp = B + (size_t)(n0 + n) * ldb + k0;
            #pragma unroll
            for (int it = 0; it < 4; it++) {
                const int kq = kq0 + it * 2;
                float4 v = *(const float4*)(bp + kq * 4);
                Bs[kq * 4 + 0][n] = f32_to_tf32(v.x);
                Bs[kq * 4 + 1][n] = f32_to_tf32(v.y);
                Bs[kq * 4 + 2][n] = f32_to_tf32(v.z);
                Bs[kq * 4 + 3][n] = f32_to_tf32(v.w);
            }
        } else {
            const int k  = tid >> 3;
            const int nq0 = tid & 7;
            const float* bp = B + (size_t)(k0 + k) * ldb + n0;
            #pragma unroll
            for (int it = 0; it < 4; it++) {
                const int n4 = (nq0 + it * 8) * 4;
                float4 v = *(const float4*)(bp + n4);
                uint4 t;
                t.x = f32_to_tf32(v.x); t.y = f32_to_tf32(v.y);
                t.z = f32_to_tf32(v.z); t.w = f32_to_tf32(v.w);
                *(uint4*)&Bs[k][n4] = t;
            }
        }
        __syncthreads();

        #pragma unroll
        for (int kb = 0; kb < 4; kb++) {
            const int kk = kb * 8;
            uint32_t a[2][4];
            #pragma unroll
            for (int mt = 0; mt < 2; mt++) {
                const int m = warp_m * 32 + mt * 16 + g;
                a[mt][0] = As[kk + c    ][m];
                a[mt][1] = As[kk + c    ][m + 8];
                a[mt][2] = As[kk + c + 4][m];
                a[mt][3] = As[kk + c + 4][m + 8];
            }
            uint32_t b[8][2];
            #pragma unroll
            for (int nt = 0; nt < 8; nt++) {
                const int n = warp_n * 64 + nt * 8 + g;
                b[nt][0] = Bs[kk + c    ][n];
                b[nt][1] = Bs[kk + c + 4][n];
            }
            #pragma unroll
            for (int mt = 0; mt < 2; mt++)
                #pragma unroll
                for (int nt = 0; nt < 8; nt++)
                    mma_tf32(acc[mt][nt], a[mt], b[nt]);
        }
        __syncthreads();
    }

    #pragma unroll
    for (int mt = 0; mt < 2; mt++) {
        const int r0 = m0 + warp_m * 32 + mt * 16 + g;
        #pragma unroll
        for (int nt = 0; nt < 8; nt++) {
            const int col = n0 + warp_n * 64 + nt * 8 + 2 * c;
            float2 bv = make_float2(0.f, 0.f);
            if (bias) bv = *(const float2*)(bias + col);
            float2 v0 = make_float2(acc[mt][nt][0] + bv.x, acc[mt][nt][1] + bv.y);
            float2 v1 = make_float2(acc[mt][nt][2] + bv.x, acc[mt][nt][3] + bv.y);
            if (RELU) {
                v0.x = fmaxf(v0.x, 0.f); v0.y = fmaxf(v0.y, 0.f);
                v1.x = fmaxf(v1.x, 0.f); v1.y = fmaxf(v1.y, 0.f);
            }
            *(float2*)(C + (size_t)r0 * ldc + col)       = v0;
            *(float2*)(C + (size_t)(r0 + 8) * ldc + col) = v1;
        }
    }
}

// ======================= fused attention (scores+softmax+AV) ======================
// One CTA = one (b,h) x 64-row i-tile. S[64,512] in smem; K/V share one buffer.
// Phase1: S = (Q K^T)*scale + mask  (tf32 MMA, warp w owns j-slab [w*64, w*64+64))
// softmax over rows in smem (tf32-rounded P), Phase2: O = P V (tf32 MMA).
#define SS_PITCH 516
#define KV_PITCH 40
#define Q_PITCH  36
#define FA_SMEM_FLOATS (64 * SS_PITCH + 512 * KV_PITCH + 64 * Q_PITCH)
#define FA_SMEM_BYTES  (FA_SMEM_FLOATS * 4)

__global__ __launch_bounds__(256)
void fused_attn_kernel(const float* __restrict__ qkv, const float* __restrict__ mask,
                       float* __restrict__ O)
{
    extern __shared__ float sm[];
    float*    Ss  = sm;
    float*    KVs = sm + 64 * SS_PITCH;
    uint32_t* Ssu = (uint32_t*)Ss;
    uint32_t* KVu = (uint32_t*)KVs;
    uint32_t* Qu  = (uint32_t*)(KVs + 512 * KV_PITCH);

    const int tid = threadIdx.x, wid = tid >> 5, lane = tid & 31;
    const int g = lane >> 2, c = lane & 3;
    const int bh = blockIdx.y, b = bh >> 3, h = bh & 7;
    const int i0 = blockIdx.x * 64;

    // ---- load Q tile (tf32) ----
    #pragma unroll
    for (int it = 0; it < 2; it++) {
        const int f = tid + it * 256;
        const int m = f >> 3, dq = (f & 7) * 4;
        float4 v = *(const float4*)(qkv + (size_t)(b * NN_ + i0 + m) * 768 + h * DHH + dq);
        Qu[m * Q_PITCH + dq + 0] = f32_to_tf32(v.x);
        Qu[m * Q_PITCH + dq + 1] = f32_to_tf32(v.y);
        Qu[m * Q_PITCH + dq + 2] = f32_to_tf32(v.z);
        Qu[m * Q_PITCH + dq + 3] = f32_to_tf32(v.w);
    }
    // ---- load K (all 512 rows, tf32) ----
    #pragma unroll
    for (int it = 0; it < 16; it++) {
        const int f = tid + it * 256;
        const int j = f >> 3, dq = (f & 7) * 4;
        float4 v = *(const float4*)(qkv + (size_t)(b * NN_ + j) * 768 + 256 + h * DHH + dq);
        KVu[j * KV_PITCH + dq + 0] = f32_to_tf32(v.x);
        KVu[j * KV_PITCH + dq + 1] = f32_to_tf32(v.y);
        KVu[j * KV_PITCH + dq + 2] = f32_to_tf32(v.z);
        KVu[j * KV_PITCH + dq + 3] = f32_to_tf32(v.w);
    }
    __syncthreads();

    // ---- phase 1: S = Q K^T over this warp's 64-col j-slab ----
    const int jb = wid * 64;
    float acc[4][8][4];
    #pragma unroll
    for (int mt = 0; mt < 4; mt++)
        #pragma unroll
        for (int nt = 0; nt < 8; nt++)
            #pragma unroll
            for (int q = 0; q < 4; q++) acc[mt][nt][q] = 0.0f;

    #pragma unroll
    for (int kb = 0; kb < 4; kb++) {
        const int kk = kb * 8;
        uint32_t a[4][4];
        #pragma unroll
        for (int mt = 0; mt < 4; mt++) {
            const int m = mt * 16 + g;
            a[mt][0] = Qu[m * Q_PITCH + kk + c];
            a[mt][1] = Qu[(m + 8) * Q_PITCH + kk + c];
            a[mt][2] = Qu[m * Q_PITCH + kk + c + 4];
            a[mt][3] = Qu[(m + 8) * Q_PITCH + kk + c + 4];
        }
        uint32_t bf[8][2];
        #pragma unroll
        for (int nt = 0; nt < 8; nt++) {
            const int j = jb + nt * 8 + g;
            bf[nt][0] = KVu[j * KV_PITCH + kk + c];
            bf[nt][1] = KVu[j * KV_PITCH + kk + c + 4];
        }
        #pragma unroll
        for (int mt = 0; mt < 4; mt++)
            #pragma unroll
            for (int nt = 0; nt < 8; nt++)
                mma_tf32(acc[mt][nt], a[mt], bf[nt]);
    }

    // ---- write S (+scale, +mask) into smem ----
    const float scale = 0.17677669529663687f;   // 1/sqrt(32)
    #pragma unroll
    for (int mt = 0; mt < 4; mt++) {
        const int r0 = mt * 16 + g;
        #pragma unroll
        for (int nt = 0; nt < 8; nt++) {
            const int col = jb + nt * 8 + 2 * c;
            float2 m0v = make_float2(0.f, 0.f), m1v = make_float2(0.f, 0.f);
            if (mask) {
                m0v = *(const float2*)(mask + (size_t)(b * NN_ + i0 + r0) * NN_ + col);
                m1v = *(const float2*)(mask + (size_t)(b * NN_ + i0 + r0 + 8) * NN_ + col);
            }
            Ss[r0 * SS_PITCH + col]           = acc[mt][nt][0] * scale + m0v.x;
            Ss[r0 * SS_PITCH + col + 1]       = acc[mt][nt][1] * scale + m0v.y;
            Ss[(r0 + 8) * SS_PITCH + col]     = acc[mt][nt][2] * scale + m1v.x;
            Ss[(r0 + 8) * SS_PITCH + col + 1] = acc[mt][nt][3] * scale + m1v.y;
        }
    }
    __syncthreads();   // all S visible; all K reads done

    // ---- load V into the K buffer (tf32) ----
    #pragma unroll
    for (int it = 0; it < 16; it++) {
        const int f = tid + it * 256;
        const int j = f >> 3, dq = (f & 7) * 4;
        float4 v = *(const float4*)(qkv + (size_t)(b * NN_ + j) * 768 + 512 + h * DHH + dq);
        KVu[j * KV_PITCH + dq + 0] = f32_to_tf32(v.x);
        KVu[j * KV_PITCH + dq + 1] = f32_to_tf32(v.y);
        KVu[j * KV_PITCH + dq + 2] = f32_to_tf32(v.z);
        KVu[j * KV_PITCH + dq + 3] = f32_to_tf32(v.w);
    }

    // ---- softmax: warp handles rows [wid*8, wid*8+8) ----
    #pragma unroll
    for (int rr = 0; rr < 8; rr++) {
        const int row = wid * 8 + rr;
        float v[16];
        float mx = -1e30f;
        #pragma unroll
        for (int t = 0; t < 16; t++) {
            v[t] = Ss[row * SS_PITCH + lane + t * 32];
            mx = fmaxf(mx, v[t]);
        }
        #pragma unroll
        for (int o = 16; o > 0; o >>= 1) mx = fmaxf(mx, __shfl_xor_sync(0xffffffffu, mx, o));
        float s = 0.0f;
        #pragma unroll
        for (int t = 0; t < 16; t++) { v[t] = __expf(v[t] - mx); s += v[t]; }
        #pragma unroll
        for (int o = 16; o > 0; o >>= 1) s += __shfl_xor_sync(0xffffffffu, s, o);
        const float inv = 1.0f / s;
        #pragma unroll
        for (int t = 0; t < 16; t++)
            Ssu[row * SS_PITCH + lane + t * 32] = f32_to_tf32(v[t] * inv);
    }
    __syncthreads();   // P (tf32) + V ready

    // ---- phase 2: O = P V.  warp: m-tile = wid>>1, n-pair base = (wid&1)*2 ----
    const int mt2 = wid >> 1;
    const int nb  = (wid & 1) * 16;    // column base within head (0 or 16)
    float o0[4] = {0.f, 0.f, 0.f, 0.f};
    float o1[4] = {0.f, 0.f, 0.f, 0.f};
    const int m = mt2 * 16 + g;
    #pragma unroll 4
    for (int ks = 0; ks < 64; ks++) {
        const int kk = ks * 8;
        uint32_t a[4];
        a[0] = Ssu[m * SS_PITCH + kk + c];
        a[1] = Ssu[(m + 8) * SS_PITCH + kk + c];
        a[2] = Ssu[m * SS_PITCH + kk + c + 4];
        a[3] = Ssu[(m + 8) * SS_PITCH + kk + c + 4];
        uint32_t bb[2];
        bb[0] = KVu[(kk + c) * KV_PITCH + nb + g];
        bb[1] = KVu[(kk + c + 4) * KV_PITCH + nb + g];
        mma_tf32(o0, a, bb);
        bb[0] = KVu[(kk + c) * KV_PITCH + nb + 8 + g];
        bb[1] = KVu[(kk + c + 4) * KV_PITCH + nb + 8 + g];
        mma_tf32(o1, a, bb);
    }
    const int r = b * NN_ + i0 + mt2 * 16 + g;
    const int colb = h * DHH + nb + 2 * c;
    *(float2*)(O + (size_t)r * DD + colb)           = make_float2(o0[0], o0[1]);
    *(float2*)(O + (size_t)(r + 8) * DD + colb)     = make_float2(o0[2], o0[3]);
    *(float2*)(O + (size_t)r * DD + colb + 8)       = make_float2(o1[0], o1[1]);
    *(float2*)(O + (size_t)(r + 8) * DD + colb + 8) = make_float2(o1[2], o1[3]);
}

// -------------------- edge MLP: sigmoid( relu(G1[src]+G2[dst]) . w2 + b2 ) --------
__global__ __launch_bounds__(256)
void edge_kernel(const float* __restrict__ G1, const float* __restrict__ G2,
                 const int* __restrict__ src, const int* __restrict__ dst,
                 const float* __restrict__ w2, const float* __restrict__ b2,
                 float* __restrict__ W)
{
    const int b = blockIdx.y;
    const int e = blockIdx.x * 8 + (threadIdx.x >> 5);
    const int lane = threadIdx.x & 31;
    const int s = src[e], d = dst[e];
    const float* g1 = G1 + ((size_t)b * NN_ + s) * DD;
    const float* g2 = G2 + ((size_t)b * NN_ + d) * DD;
    float acc = 0.0f;
    #pragma unroll
    for (int q = 0; q < 2; q++) {
        const int t = lane * 8 + q * 4;
        float4 a = *(const float4*)(g1 + t);
        float4 c = *(const float4*)(g2 + t);
        float4 w = *(const float4*)(w2 + t);
        acc += fmaxf(a.x + c.x, 0.0f) * w.x + fmaxf(a.y + c.y, 0.0f) * w.y
             + fmaxf(a.z + c.z, 0.0f) * w.z + fmaxf(a.w + c.w, 0.0f) * w.w;
    }
    #pragma unroll
    for (int o = 16; o > 0; o >>= 1) acc += __shfl_xor_sync(0xffffffffu, acc, o);
    if (lane == 0) {
        const float v = 1.0f / (1.0f + __expf(-(acc + b2[0])));
        W[((size_t)b * NN_ + s) * NN_ + d] = v;
    }
}

// -------------------- consistency reduce: sigmoid(H . cw2 + cb2) -------------------
__global__ __launch_bounds__(256)
void cons_reduce_kernel(const float* __restrict__ Hbuf, const float* __restrict__ cw2,
                        const float* __restrict__ cb2, float* __restrict__ out)
{
    __shared__ float red[256];
    const int row = blockIdx.x;
    const int t = threadIdx.x;
    red[t] = Hbuf[(size_t)row * DD + t] * __ldg(cw2 + t);
    __syncthreads();
    for (int s = 128; s > 0; s >>= 1) { if (t < s) red[t] += red[t + s]; __syncthreads(); }
    if (t == 0) out[row] = 1.0f / (1.0f + __expf(-(red[0] + cb2[0])));
}

// -------------------- zero fill ----------------------------------------------------
__global__ void zero_kernel(float* __restrict__ p, size_t n)
{
    size_t i = (size_t)blockIdx.x * blockDim.x + threadIdx.x;
    const size_t stride = (size_t)gridDim.x * blockDim.x;
    for (; i < n; i += stride) p[i] = 0.0f;
}

// ===================================================================================
extern "C" void kernel_launch(void* const* d_in, const int* in_sizes, int n_in,
                              void* d_out, int out_size)
{
    const float* img   = (const float*)d_in[0];
    const float* txt   = (const float*)d_in[1];
    const int*   src   = (const int*)d_in[2];
    const int*   dst   = (const int*)d_in[3];
    const float* w1    = (const float*)d_in[4];
    const float* b1    = (const float*)d_in[5];
    const float* w2    = (const float*)d_in[6];
    const float* b2    = (const float*)d_in[7];
    const float* in_w  = (const float*)d_in[8];
    const float* in_b  = (const float*)d_in[9];
    const float* out_w = (const float*)d_in[10];
    const float* out_b = (const float*)d_in[11];
    const float* cw1   = (const float*)d_in[12];
    const float* cb1   = (const float*)d_in[13];
    const float* cw2   = (const float*)d_in[14];
    const float* cb2   = (const float*)d_in[15];
    float* out = (float*)d_out;

    float *qkv, *attn, *G1, *G2, *Hb;
    cudaGetSymbolAddress((void**)&qkv,  g_qkv);
    cudaGetSymbolAddress((void**)&attn, g_attn);
    cudaGetSymbolAddress((void**)&G1,   g_G1);
    cudaGetSymbolAddress((void**)&G2,   g_G2);
    cudaGetSymbolAddress((void**)&Hb,   g_H);

    static bool attr_done = false;
    if (!attr_done) {
        cudaFuncSetAttribute(fused_attn_kernel,
                             cudaFuncAttributeMaxDynamicSharedMemorySize, FA_SMEM_BYTES);
        attr_done = true;
    }

    const dim3 blk(256);
    const dim3 g_gemm256(256 / 128, BN / 128);
    const dim3 g_gemm512(512 / 128, BN / 128);
    const dim3 g_gemm768(768 / 128, BN / 128);
    const dim3 g_fa(NN_ / 64, BB * HH);        // (8, 128)
    const dim3 g_edge(EE / 8, BB);

    // ---- zero the two adjacency-weight output blocks (contiguous) ----
    zero_kernel<<<2048, 256>>>(out + O_IW, (size_t)2 * BB * NN_ * NN_);

    // ---- causal weights (algebraic split: G1 = f@w1[:256]+b1, G2 = f@w1[256:]) ----
    gemm_tf32_kernel<false, false><<<g_gemm256, blk>>>(img, w1,            b1,      G1, BN, 256, 256, 256, 256, 256);
    gemm_tf32_kernel<false, false><<<g_gemm256, blk>>>(img, w1 + 256*256, nullptr,  G2, BN, 256, 256, 256, 256, 256);
    edge_kernel<<<g_edge, blk>>>(G1, G2, src, dst, w2, b2, out + O_IW);
    gemm_tf32_kernel<false, false><<<g_gemm256, blk>>>(txt, w1,            b1,      G1, BN, 256, 256, 256, 256, 256);
    gemm_tf32_kernel<false, false><<<g_gemm256, blk>>>(txt, w1 + 256*256, nullptr,  G2, BN, 256, 256, 256, 256, 256);
    edge_kernel<<<g_edge, blk>>>(G1, G2, src, dst, w2, b2, out + O_TW);

    // ---- MHA 1: attended_img ----
    gemm_tf32_kernel<true, false><<<g_gemm768, blk>>>(img, in_w, in_b, qkv, BN, 768, 256, 256, 256, 768);
    fused_attn_kernel<<<g_fa, blk, FA_SMEM_BYTES>>>(qkv, out + O_IW, attn);
    gemm_tf32_kernel<true, false><<<g_gemm256, blk>>>(attn, out_w, out_b, out + O_AIMG, BN, 256, 256, 256, 256, 256);

    // ---- MHA 2: attended_text ----
    gemm_tf32_kernel<true, false><<<g_gemm768, blk>>>(txt, in_w, in_b, qkv, BN, 768, 256, 256, 256, 768);
    fused_attn_kernel<<<g_fa, blk, FA_SMEM_BYTES>>>(qkv, out + O_TW, attn);
    gemm_tf32_kernel<true, false><<<g_gemm256, blk>>>(attn, out_w, out_b, out + O_ATXT, BN, 256, 256, 256, 256, 256);

    // ---- MHA 3: cross_modal (q from attended_img, k|v from attended_text) ----
    gemm_tf32_kernel<true, false><<<g_gemm256, blk>>>(out + O_AIMG, in_w,           in_b,       qkv,       BN, 256, 256, 256, 256, 768);
    gemm_tf32_kernel<true, false><<<g_gemm512, blk>>>(out + O_ATXT, in_w + 256*256, in_b + 256, qkv + 256, BN, 512, 256, 256, 256, 768);
    fused_attn_kernel<<<g_fa, blk, FA_SMEM_BYTES>>>(qkv, nullptr, attn);
    gemm_tf32_kernel<true, false><<<g_gemm256, blk>>>(attn, out_w, out_b, out + O_XMOD, BN, 256, 256, 256, 256, 256);

    // ---- consistency heads ----
    gemm_tf32_kernel<false, true><<<g_gemm256, blk>>>(out + O_AIMG, cw1, cb1, Hb, BN, 256, 256, 256, 256, 256);
    cons_reduce_kernel<<<BN, blk>>>(Hb, cw2, cb2, out + O_IC);
    gemm_tf32_kernel<false, true><<<g_gemm256, blk>>>(out + O_ATXT, cw1, cb1, Hb, BN, 256, 256, 256, 256, 256);
    cons_reduce_kernel<<<BN, blk>>>(Hb, cw2, cb2, out + O_TC);
}

// round 5
// speedup vs baseline: 2.9773x; 1.2705x over previous
#include <cuda_runtime.h>
#include <cuda_bf16.h>
#include <cstdint>
#include <cstddef>

// Problem constants
#define BB 16
#define NN_ 512
#define DD 256
#define HH 8
#define DHH 32
#define EE 16384
#define BN (BB * NN_)          // 8192

// Output layout (flattened tuple, in reference return order)
#define O_AIMG 0
#define O_ATXT 2097152
#define O_XMOD 4194304
#define O_IW   6291456
#define O_TW   10485760
#define O_IC   14680064
#define O_TC   14688256

// -------------------- static scratch (no allocations allowed) --------------------
__device__ float g_qkv0[BN * 768];
__device__ float g_qkv1[BN * 768];
__device__ float g_attn0[BN * DD];
__device__ float g_attn1[BN * DD];
__device__ float g_G1i[BN * DD];
__device__ float g_G2i[BN * DD];
__device__ float g_G1t[BN * DD];
__device__ float g_G2t[BN * DD];
__device__ float g_H0[BN * DD];
__device__ float g_H1[BN * DD];

__device__ __forceinline__ uint32_t f32_to_tf32(float x) {
    uint32_t r;
    asm("cvt.rna.tf32.f32 %0, %1;" : "=r"(r) : "f"(x));
    return r;
}

__device__ __forceinline__ void mma_tf32(float* d, const uint32_t* a, const uint32_t* b) {
    asm volatile(
        "mma.sync.aligned.m16n8k8.row.col.f32.tf32.tf32.f32 "
        "{%0,%1,%2,%3}, {%4,%5,%6,%7}, {%8,%9}, {%0,%1,%2,%3};"
        : "+f"(d[0]), "+f"(d[1]), "+f"(d[2]), "+f"(d[3])
        : "r"(a[0]), "r"(a[1]), "r"(a[2]), "r"(a[3]), "r"(b[0]), "r"(b[1]));
}

__device__ __forceinline__ void cp_async16(void* smem, const void* gmem) {
    uint32_t s = (uint32_t)__cvta_generic_to_shared(smem);
    asm volatile("cp.async.ca.shared.global [%0], [%1], 16;" :: "r"(s), "l"(gmem));
}
__device__ __forceinline__ void cp_commit() {
    asm volatile("cp.async.commit_group;");
}
template <int N>
__device__ __forceinline__ void cp_wait() {
    asm volatile("cp.async.wait_group %0;" :: "n"(N));
}

// ===================== batched, pipelined TF32 tensor-core GEMM ====================
// C[M,N] = A[M,K=256] @ B(^T) + bias, optional ReLU, fp32 in/out, tf32 MMA.
// A: [M,256] row-major. B: TRANSB -> [N,256]; else [256,N] (ldb=256).
// blockIdx.z selects a (A,B,bias,C,N,ldc) slice. CTA tile 128x128, 2-stage cp.async.
struct GemmP { const float* A; const float* B; const float* bias; float* C; int N; int ldc; };
struct GemmBatch { GemmP p[4]; };

#define AP 36     // A smem pitch (floats):   bank stride 4 -> conflict-free frags
#define BPT 36    // B smem pitch, TRANSB
#define BPN 136   // B smem pitch, non-trans: bank stride 8 -> conflict-free frags
#define A_STG (128 * AP)
#define BT_STG (128 * BPT)
#define BN_STG (32 * BPN)
#define SMEM_GEMM_T ((2 * A_STG + 2 * BT_STG) * 4)
#define SMEM_GEMM_N ((2 * A_STG + 2 * BN_STG) * 4)

template <bool TRANSB, bool RELU>
__global__ __launch_bounds__(256, 2)
void gemm_tf32_kernel(GemmBatch args)
{
    const GemmP p = args.p[blockIdx.z];
    const int n0 = blockIdx.x * 128;
    if (n0 >= p.N) return;
    const int m0 = blockIdx.y * 128;

    extern __shared__ float smf[];
    float* Asb[2] = { smf, smf + A_STG };
    float* Bsb[2] = { smf + 2 * A_STG,
                      smf + 2 * A_STG + (TRANSB ? BT_STG : BN_STG) };

    const int tid  = threadIdx.x;
    const int wid  = tid >> 5;
    const int lane = tid & 31;
    const int g    = lane >> 2;
    const int c    = lane & 3;
    const int warp_m = wid >> 1;
    const int warp_n = wid & 1;

    const float* A = p.A;
    const float* B = p.B;

    auto issue = [&](int k0, float* Ad, float* Bd) {
        // A tile: 128 rows x 32 floats = 1024 x 16B chunks
        #pragma unroll
        for (int it = 0; it < 4; it++) {
            const int ch = tid + it * 256;
            const int row = ch >> 3, kq = ch & 7;
            cp_async16(Ad + row * AP + kq * 4,
                       A + (size_t)(m0 + row) * 256 + k0 + kq * 4);
        }
        if (TRANSB) {
            // B tile: 128 rows x 32 floats = 1024 chunks
            #pragma unroll
            for (int it = 0; it < 4; it++) {
                const int ch = tid + it * 256;
                const int row = ch >> 3, kq = ch & 7;
                cp_async16(Bd + row * BPT + kq * 4,
                           B + (size_t)(n0 + row) * 256 + k0 + kq * 4);
            }
        } else {
            // B tile: 32 rows x 128 floats = 1024 chunks
            #pragma unroll
            for (int it = 0; it < 4; it++) {
                const int ch = tid + it * 256;
                const int row = ch >> 5, nq = ch & 31;
                cp_async16(Bd + row * BPN + nq * 4,
                           B + (size_t)(k0 + row) * 256 + n0 + nq * 4);
            }
        }
    };

    float acc[2][8][4];
    #pragma unroll
    for (int i = 0; i < 2; i++)
        #pragma unroll
        for (int j = 0; j < 8; j++)
            #pragma unroll
            for (int q = 0; q < 4; q++) acc[i][j][q] = 0.0f;

    issue(0, Asb[0], Bsb[0]);
    cp_commit();

    #pragma unroll 1
    for (int iter = 0; iter < 8; iter++) {
        float* Ad = Asb[iter & 1];
        float* Bd = Bsb[iter & 1];
        if (iter < 7) {
            issue((iter + 1) * 32, Asb[(iter + 1) & 1], Bsb[(iter + 1) & 1]);
            cp_commit();
            cp_wait<1>();
        } else {
            cp_wait<0>();
        }
        __syncthreads();

        #pragma unroll
        for (int kb = 0; kb < 4; kb++) {
            const int kk = kb * 8;
            uint32_t a[2][4];
            #pragma unroll
            for (int mt = 0; mt < 2; mt++) {
                const int m = warp_m * 32 + mt * 16 + g;
                a[mt][0] = f32_to_tf32(Ad[m * AP + kk + c]);
                a[mt][1] = f32_to_tf32(Ad[(m + 8) * AP + kk + c]);
                a[mt][2] = f32_to_tf32(Ad[m * AP + kk + c + 4]);
                a[mt][3] = f32_to_tf32(Ad[(m + 8) * AP + kk + c + 4]);
            }
            uint32_t bf[8][2];
            #pragma unroll
            for (int nt = 0; nt < 8; nt++) {
                const int n = warp_n * 64 + nt * 8 + g;
                if (TRANSB) {
                    bf[nt][0] = f32_to_tf32(Bd[n * BPT + kk + c]);
                    bf[nt][1] = f32_to_tf32(Bd[n * BPT + kk + c + 4]);
                } else {
                    bf[nt][0] = f32_to_tf32(Bd[(kk + c) * BPN + n]);
                    bf[nt][1] = f32_to_tf32(Bd[(kk + c + 4) * BPN + n]);
                }
            }
            #pragma unroll
            for (int mt = 0; mt < 2; mt++)
                #pragma unroll
                for (int nt = 0; nt < 8; nt++)
                    mma_tf32(acc[mt][nt], a[mt], bf[nt]);
        }
        __syncthreads();
    }

    #pragma unroll
    for (int mt = 0; mt < 2; mt++) {
        const int r0 = m0 + warp_m * 32 + mt * 16 + g;
        #pragma unroll
        for (int nt = 0; nt < 8; nt++) {
            const int col = n0 + warp_n * 64 + nt * 8 + 2 * c;
            float2 bv = make_float2(0.f, 0.f);
            if (p.bias) bv = *(const float2*)(p.bias + col);
            float2 v0 = make_float2(acc[mt][nt][0] + bv.x, acc[mt][nt][1] + bv.y);
            float2 v1 = make_float2(acc[mt][nt][2] + bv.x, acc[mt][nt][3] + bv.y);
            if (RELU) {
                v0.x = fmaxf(v0.x, 0.f); v0.y = fmaxf(v0.y, 0.f);
                v1.x = fmaxf(v1.x, 0.f); v1.y = fmaxf(v1.y, 0.f);
            }
            *(float2*)(p.C + (size_t)r0 * p.ldc + col)       = v0;
            *(float2*)(p.C + (size_t)(r0 + 8) * p.ldc + col) = v1;
        }
    }
}

// ======================= fused attention (scores+softmax+AV) ======================
#define SS_PITCH 516
#define KV_PITCH 40
#define Q_PITCH  36
#define FA_SMEM_FLOATS (64 * SS_PITCH + 512 * KV_PITCH + 64 * Q_PITCH)
#define FA_SMEM_BYTES  (FA_SMEM_FLOATS * 4)

__global__ __launch_bounds__(256)
void fused_attn_kernel(const float* __restrict__ qkvA, const float* __restrict__ qkvB,
                       const float* __restrict__ maskA, const float* __restrict__ maskB,
                       float* __restrict__ OA, float* __restrict__ OB)
{
    const float* qkv  = blockIdx.z ? qkvB  : qkvA;
    const float* mask = blockIdx.z ? maskB : maskA;
    float*       O    = blockIdx.z ? OB    : OA;

    extern __shared__ float sm[];
    float*    Ss  = sm;
    float*    KVs = sm + 64 * SS_PITCH;
    uint32_t* Ssu = (uint32_t*)Ss;
    uint32_t* KVu = (uint32_t*)KVs;
    uint32_t* Qu  = (uint32_t*)(KVs + 512 * KV_PITCH);

    const int tid = threadIdx.x, wid = tid >> 5, lane = tid & 31;
    const int g = lane >> 2, c = lane & 3;
    const int bh = blockIdx.y, b = bh >> 3, h = bh & 7;
    const int i0 = blockIdx.x * 64;

    #pragma unroll
    for (int it = 0; it < 2; it++) {
        const int f = tid + it * 256;
        const int m = f >> 3, dq = (f & 7) * 4;
        float4 v = *(const float4*)(qkv + (size_t)(b * NN_ + i0 + m) * 768 + h * DHH + dq);
        Qu[m * Q_PITCH + dq + 0] = f32_to_tf32(v.x);
        Qu[m * Q_PITCH + dq + 1] = f32_to_tf32(v.y);
        Qu[m * Q_PITCH + dq + 2] = f32_to_tf32(v.z);
        Qu[m * Q_PITCH + dq + 3] = f32_to_tf32(v.w);
    }
    #pragma unroll
    for (int it = 0; it < 16; it++) {
        const int f = tid + it * 256;
        const int j = f >> 3, dq = (f & 7) * 4;
        float4 v = *(const float4*)(qkv + (size_t)(b * NN_ + j) * 768 + 256 + h * DHH + dq);
        KVu[j * KV_PITCH + dq + 0] = f32_to_tf32(v.x);
        KVu[j * KV_PITCH + dq + 1] = f32_to_tf32(v.y);
        KVu[j * KV_PITCH + dq + 2] = f32_to_tf32(v.z);
        KVu[j * KV_PITCH + dq + 3] = f32_to_tf32(v.w);
    }
    __syncthreads();

    const int jb = wid * 64;
    float acc[4][8][4];
    #pragma unroll
    for (int mt = 0; mt < 4; mt++)
        #pragma unroll
        for (int nt = 0; nt < 8; nt++)
            #pragma unroll
            for (int q = 0; q < 4; q++) acc[mt][nt][q] = 0.0f;

    #pragma unroll
    for (int kb = 0; kb < 4; kb++) {
        const int kk = kb * 8;
        uint32_t a[4][4];
        #pragma unroll
        for (int mt = 0; mt < 4; mt++) {
            const int m = mt * 16 + g;
            a[mt][0] = Qu[m * Q_PITCH + kk + c];
            a[mt][1] = Qu[(m + 8) * Q_PITCH + kk + c];
            a[mt][2] = Qu[m * Q_PITCH + kk + c + 4];
            a[mt][3] = Qu[(m + 8) * Q_PITCH + kk + c + 4];
        }
        uint32_t bf[8][2];
        #pragma unroll
        for (int nt = 0; nt < 8; nt++) {
            const int j = jb + nt * 8 + g;
            bf[nt][0] = KVu[j * KV_PITCH + kk + c];
            bf[nt][1] = KVu[j * KV_PITCH + kk + c + 4];
        }
        #pragma unroll
        for (int mt = 0; mt < 4; mt++)
            #pragma unroll
            for (int nt = 0; nt < 8; nt++)
                mma_tf32(acc[mt][nt], a[mt], bf[nt]);
    }

    const float scale = 0.17677669529663687f;   // 1/sqrt(32)
    #pragma unroll
    for (int mt = 0; mt < 4; mt++) {
        const int r0 = mt * 16 + g;
        #pragma unroll
        for (int nt = 0; nt < 8; nt++) {
            const int col = jb + nt * 8 + 2 * c;
            float2 m0v = make_float2(0.f, 0.f), m1v = make_float2(0.f, 0.f);
            if (mask) {
                m0v = *(const float2*)(mask + (size_t)(b * NN_ + i0 + r0) * NN_ + col);
                m1v = *(const float2*)(mask + (size_t)(b * NN_ + i0 + r0 + 8) * NN_ + col);
            }
            Ss[r0 * SS_PITCH + col]           = acc[mt][nt][0] * scale + m0v.x;
            Ss[r0 * SS_PITCH + col + 1]       = acc[mt][nt][1] * scale + m0v.y;
            Ss[(r0 + 8) * SS_PITCH + col]     = acc[mt][nt][2] * scale + m1v.x;
            Ss[(r0 + 8) * SS_PITCH + col + 1] = acc[mt][nt][3] * scale + m1v.y;
        }
    }
    __syncthreads();

    #pragma unroll
    for (int it = 0; it < 16; it++) {
        const int f = tid + it * 256;
        const int j = f >> 3, dq = (f & 7) * 4;
        float4 v = *(const float4*)(qkv + (size_t)(b * NN_ + j) * 768 + 512 + h * DHH + dq);
        KVu[j * KV_PITCH + dq + 0] = f32_to_tf32(v.x);
        KVu[j * KV_PITCH + dq + 1] = f32_to_tf32(v.y);
        KVu[j * KV_PITCH + dq + 2] = f32_to_tf32(v.z);
        KVu[j * KV_PITCH + dq + 3] = f32_to_tf32(v.w);
    }

    #pragma unroll
    for (int rr = 0; rr < 8; rr++) {
        const int row = wid * 8 + rr;
        float v[16];
        float mx = -1e30f;
        #pragma unroll
        for (int t = 0; t < 16; t++) {
            v[t] = Ss[row * SS_PITCH + lane + t * 32];
            mx = fmaxf(mx, v[t]);
        }
        #pragma unroll
        for (int o = 16; o > 0; o >>= 1) mx = fmaxf(mx, __shfl_xor_sync(0xffffffffu, mx, o));
        float s = 0.0f;
        #pragma unroll
        for (int t = 0; t < 16; t++) { v[t] = __expf(v[t] - mx); s += v[t]; }
        #pragma unroll
        for (int o = 16; o > 0; o >>= 1) s += __shfl_xor_sync(0xffffffffu, s, o);
        const float inv = 1.0f / s;
        #pragma unroll
        for (int t = 0; t < 16; t++)
            Ssu[row * SS_PITCH + lane + t * 32] = f32_to_tf32(v[t] * inv);
    }
    __syncthreads();

    const int mt2 = wid >> 1;
    const int nb  = (wid & 1) * 16;
    float o0[4] = {0.f, 0.f, 0.f, 0.f};
    float o1[4] = {0.f, 0.f, 0.f, 0.f};
    const int m = mt2 * 16 + g;
    #pragma unroll 4
    for (int ks = 0; ks < 64; ks++) {
        const int kk = ks * 8;
        uint32_t a[4];
        a[0] = Ssu[m * SS_PITCH + kk + c];
        a[1] = Ssu[(m + 8) * SS_PITCH + kk + c];
        a[2] = Ssu[m * SS_PITCH + kk + c + 4];
        a[3] = Ssu[(m + 8) * SS_PITCH + kk + c + 4];
        uint32_t bb[2];
        bb[0] = KVu[(kk + c) * KV_PITCH + nb + g];
        bb[1] = KVu[(kk + c + 4) * KV_PITCH + nb + g];
        mma_tf32(o0, a, bb);
        bb[0] = KVu[(kk + c) * KV_PITCH + nb + 8 + g];
        bb[1] = KVu[(kk + c + 4) * KV_PITCH + nb + 8 + g];
        mma_tf32(o1, a, bb);
    }
    const int r = b * NN_ + i0 + mt2 * 16 + g;
    const int colb = h * DHH + nb + 2 * c;
    *(float2*)(O + (size_t)r * DD + colb)           = make_float2(o0[0], o0[1]);
    *(float2*)(O + (size_t)(r + 8) * DD + colb)     = make_float2(o0[2], o0[3]);
    *(float2*)(O + (size_t)r * DD + colb + 8)       = make_float2(o1[0], o1[1]);
    *(float2*)(O + (size_t)(r + 8) * DD + colb + 8) = make_float2(o1[2], o1[3]);
}

// -------------------- edge MLP: sigmoid( relu(G1[src]+G2[dst]) . w2 + b2 ) --------
// Batched (z: img/text); 8 edges per warp; w2 cached in registers.
__global__ __launch_bounds__(256)
void edge_kernel(const float* __restrict__ G1a, const float* __restrict__ G2a,
                 const float* __restrict__ G1b, const float* __restrict__ G2b,
                 const int* __restrict__ src, const int* __restrict__ dst,
                 const float* __restrict__ w2, const float* __restrict__ b2,
                 float* __restrict__ Wa, float* __restrict__ Wb)
{
    const float* G1 = blockIdx.z ? G1b : G1a;
    const float* G2 = blockIdx.z ? G2b : G2a;
    float*       W  = blockIdx.z ? Wb  : Wa;
    const int b = blockIdx.y;
    const int wid = threadIdx.x >> 5, lane = threadIdx.x & 31;

    float4 wv0 = *(const float4*)(w2 + lane * 8);
    float4 wv1 = *(const float4*)(w2 + lane * 8 + 4);
    const float bias = b2[0];
    const int e0 = blockIdx.x * 64 + wid * 8;

    #pragma unroll 1
    for (int i = 0; i < 8; i++) {
        const int e = e0 + i;
        const int s = src[e], d = dst[e];
        const float* g1 = G1 + ((size_t)b * NN_ + s) * DD + lane * 8;
        const float* g2 = G2 + ((size_t)b * NN_ + d) * DD + lane * 8;
        float4 a0 = *(const float4*)(g1);
        float4 a1 = *(const float4*)(g1 + 4);
        float4 c0 = *(const float4*)(g2);
        float4 c1 = *(const float4*)(g2 + 4);
        float acc = fmaxf(a0.x + c0.x, 0.f) * wv0.x + fmaxf(a0.y + c0.y, 0.f) * wv0.y
                  + fmaxf(a0.z + c0.z, 0.f) * wv0.z + fmaxf(a0.w + c0.w, 0.f) * wv0.w
                  + fmaxf(a1.x + c1.x, 0.f) * wv1.x + fmaxf(a1.y + c1.y, 0.f) * wv1.y
                  + fmaxf(a1.z + c1.z, 0.f) * wv1.z + fmaxf(a1.w + c1.w, 0.f) * wv1.w;
        #pragma unroll
        for (int o = 16; o > 0; o >>= 1) acc += __shfl_xor_sync(0xffffffffu, acc, o);
        if (lane == 0) {
            const float v = 1.0f / (1.0f + __expf(-(acc + bias)));
            W[((size_t)b * NN_ + s) * NN_ + d] = v;
        }
    }
}

// -------------------- consistency reduce: sigmoid(H . cw2 + cb2), batched ---------
__global__ __launch_bounds__(256)
void cons_reduce_kernel(const float* __restrict__ H0, const float* __restrict__ H1,
                        const float* __restrict__ cw2, const float* __restrict__ cb2,
                        float* __restrict__ o0, float* __restrict__ o1)
{
    const float* Hbuf = blockIdx.y ? H1 : H0;
    float* out        = blockIdx.y ? o1 : o0;
    __shared__ float red[256];
    const int row = blockIdx.x;
    const int t = threadIdx.x;
    red[t] = Hbuf[(size_t)row * DD + t] * __ldg(cw2 + t);
    __syncthreads();
    for (int s = 128; s > 0; s >>= 1) { if (t < s) red[t] += red[t + s]; __syncthreads(); }
    if (t == 0) out[row] = 1.0f / (1.0f + __expf(-(red[0] + cb2[0])));
}

// -------------------- zero fill ----------------------------------------------------
__global__ void zero_kernel(float* __restrict__ p, size_t n)
{
    size_t i = (size_t)blockIdx.x * blockDim.x + threadIdx.x;
    const size_t stride = (size_t)gridDim.x * blockDim.x;
    for (; i < n; i += stride) p[i] = 0.0f;
}

// ===================================================================================
extern "C" void kernel_launch(void* const* d_in, const int* in_sizes, int n_in,
                              void* d_out, int out_size)
{
    const float* img   = (const float*)d_in[0];
    const float* txt   = (const float*)d_in[1];
    const int*   src   = (const int*)d_in[2];
    const int*   dst   = (const int*)d_in[3];
    const float* w1    = (const float*)d_in[4];
    const float* b1    = (const float*)d_in[5];
    const float* w2    = (const float*)d_in[6];
    const float* b2    = (const float*)d_in[7];
    const float* in_w  = (const float*)d_in[8];
    const float* in_b  = (const float*)d_in[9];
    const float* out_w = (const float*)d_in[10];
    const float* out_b = (const float*)d_in[11];
    const float* cw1   = (const float*)d_in[12];
    const float* cb1   = (const float*)d_in[13];
    const float* cw2   = (const float*)d_in[14];
    const float* cb2   = (const float*)d_in[15];
    float* out = (float*)d_out;

    float *qkv0, *qkv1, *attn0, *attn1, *G1i, *G2i, *G1t, *G2t, *H0, *H1;
    cudaGetSymbolAddress((void**)&qkv0,  g_qkv0);
    cudaGetSymbolAddress((void**)&qkv1,  g_qkv1);
    cudaGetSymbolAddress((void**)&attn0, g_attn0);
    cudaGetSymbolAddress((void**)&attn1, g_attn1);
    cudaGetSymbolAddress((void**)&G1i,   g_G1i);
    cudaGetSymbolAddress((void**)&G2i,   g_G2i);
    cudaGetSymbolAddress((void**)&G1t,   g_G1t);
    cudaGetSymbolAddress((void**)&G2t,   g_G2t);
    cudaGetSymbolAddress((void**)&H0,    g_H0);
    cudaGetSymbolAddress((void**)&H1,    g_H1);

    cudaFuncSetAttribute(fused_attn_kernel,
                         cudaFuncAttributeMaxDynamicSharedMemorySize, FA_SMEM_BYTES);
    cudaFuncSetAttribute(gemm_tf32_kernel<true, false>,
                         cudaFuncAttributeMaxDynamicSharedMemorySize, SMEM_GEMM_T);
    cudaFuncSetAttribute(gemm_tf32_kernel<false, false>,
                         cudaFuncAttributeMaxDynamicSharedMemorySize, SMEM_GEMM_N);
    cudaFuncSetAttribute(gemm_tf32_kernel<false, true>,
                         cudaFuncAttributeMaxDynamicSharedMemorySize, SMEM_GEMM_N);

    const dim3 blk(256);

    // ---- zero the two adjacency-weight output blocks (contiguous) ----
    zero_kernel<<<2048, 256>>>(out + O_IW, (size_t)2 * BB * NN_ * NN_);

    // ---- causal-weight node projections: 4 batched GEMMs ----
    {
        GemmBatch gb;
        gb.p[0] = { img, w1,             b1,      G1i, 256, 256 };
        gb.p[1] = { img, w1 + 256 * 256, nullptr, G2i, 256, 256 };
        gb.p[2] = { txt, w1,             b1,      G1t, 256, 256 };
        gb.p[3] = { txt, w1 + 256 * 256, nullptr, G2t, 256, 256 };
        gemm_tf32_kernel<false, false><<<dim3(2, 64, 4), blk, SMEM_GEMM_N>>>(gb);
    }
    edge_kernel<<<dim3(EE / 64, BB, 2), blk>>>(G1i, G2i, G1t, G2t, src, dst, w2, b2,
                                               out + O_IW, out + O_TW);

    // ---- qkv projections for MHA1+MHA2 (batched) ----
    {
        GemmBatch gb;
        gb.p[0] = { img, in_w, in_b, qkv0, 768, 768 };
        gb.p[1] = { txt, in_w, in_b, qkv1, 768, 768 };
        gb.p[2] = gb.p[0]; gb.p[3] = gb.p[0];
        gemm_tf32_kernel<true, false><<<dim3(6, 64, 2), blk, SMEM_GEMM_T>>>(gb);
    }
    // ---- fused attention MHA1+MHA2 (batched) ----
    fused_attn_kernel<<<dim3(8, 128, 2), blk, FA_SMEM_BYTES>>>(
        qkv0, qkv1, out + O_IW, out + O_TW, attn0, attn1);
    // ---- out-proj MHA1+MHA2 (batched) ----
    {
        GemmBatch gb;
        gb.p[0] = { attn0, out_w, out_b, out + O_AIMG, 256, 256 };
        gb.p[1] = { attn1, out_w, out_b, out + O_ATXT, 256, 256 };
        gb.p[2] = gb.p[0]; gb.p[3] = gb.p[0];
        gemm_tf32_kernel<true, false><<<dim3(2, 64, 2), blk, SMEM_GEMM_T>>>(gb);
    }

    // ---- consistency heads (independent of MHA3) ----
    {
        GemmBatch gb;
        gb.p[0] = { out + O_AIMG, cw1, cb1, H0, 256, 256 };
        gb.p[1] = { out + O_ATXT, cw1, cb1, H1, 256, 256 };
        gb.p[2] = gb.p[0]; gb.p[3] = gb.p[0];
        gemm_tf32_kernel<false, true><<<dim3(2, 64, 2), blk, SMEM_GEMM_N>>>(gb);
    }
    cons_reduce_kernel<<<dim3(BN, 2), blk>>>(H0, H1, cw2, cb2, out + O_IC, out + O_TC);

    // ---- MHA3 projections: q from attended_img; k|v from attended_text ----
    {
        GemmBatch gb;
        gb.p[0] = { out + O_AIMG, in_w,             in_b,       qkv0,       256, 768 };
        gb.p[1] = { out + O_ATXT, in_w + 256 * 256, in_b + 256, qkv0 + 256, 512, 768 };
        gb.p[2] = gb.p[0]; gb.p[3] = gb.p[0];
        gemm_tf32_kernel<true, false><<<dim3(4, 64, 2), blk, SMEM_GEMM_T>>>(gb);
    }
    fused_attn_kernel<<<dim3(8, 128, 1), blk, FA_SMEM_BYTES>>>(
        qkv0, qkv0, nullptr, nullptr, attn0, attn0);
    {
        GemmBatch gb;
        gb.p[0] = { attn0, out_w, out_b, out + O_XMOD, 256, 256 };
        gb.p[1] = gb.p[0]; gb.p[2] = gb.p[0]; gb.p[3] = gb.p[0];
        gemm_tf32_kernel<true, false><<<dim3(2, 64, 1), blk, SMEM_GEMM_T>>>(gb);
    }
}